// round 10
// baseline (speedup 1.0000x reference)
#include <cuda_runtime.h>
#include <cstddef>

// CAN: per-sample 2-layer MLP, B=16384, N=50, D=16, fp32.
// x = relu(x @ W0 + b0); x = relu(x @ W1 + b1)
//
// R9: R8 compute core (quad lane owns 10 rows x 4 cols) with both ends
// moved to the TMA bulk engine: cp.async.bulk + mbarrier stage-in,
// STS + cp.async.bulk.global stage-out. Bias folded into first FMA2.

#define CAN_D 16
#define CAN_N 50
#define SPB 8                 // samples per block
#define TPB 160               // 8 samples * 20 lanes
#define XBLK 164              // floats per 10-row block (160 data + 4 pad)
#define X_STRIDE 820          // 5 blocks * 164 floats per sample
#define W_FLOATS 544
#define W_STRIDE 560          // mod 32 banks = 16 -> straddle-conflict-free

typedef unsigned long long ull;

#define FMA2(acc, x2, w2) \
    asm("fma.rn.f32x2 %0, %1, %2, %3;" : "=l"(acc) : "l"(x2), "l"(w2), "l"(acc))
#define FMA2_INIT(dst, x2, w2, add) \
    asm("fma.rn.f32x2 %0, %1, %2, %3;" : "=l"(dst) : "l"(x2), "l"(w2), "l"(add))

__device__ __forceinline__ ull pack2(float a, float b) {
    ull r; asm("mov.b64 %0, {%1, %2};" : "=l"(r) : "f"(a), "f"(b)); return r;
}
__device__ __forceinline__ ull splat2(float a) {
    ull r; asm("mov.b64 %0, {%1, %1};" : "=l"(r) : "f"(a)); return r;
}
__device__ __forceinline__ void unpack2(ull p, float& lo, float& hi) {
    asm("mov.b64 {%0, %1}, %2;" : "=f"(lo), "=f"(hi) : "l"(p));
}

// One layer for lane's 10 rows x 4 cols, bias as FMA addend on first chunk.
__device__ __forceinline__ void can_core(const float4* __restrict__ wl,
                                         const float* __restrict__ xrow,
                                         int ch, ull acc[10][2])
{
    float4 bv = wl[64 + ch];
    ull b0 = pack2(bv.x, bv.y), b1 = pack2(bv.z, bv.w);

    #pragma unroll
    for (int dc = 0; dc < 4; ++dc) {              // 4 d's per chunk
        ull wu[4][2];                             // 16 regs
        #pragma unroll
        for (int k = 0; k < 4; ++k) {
            float4 w = wl[(4 * dc + k) * 4 + ch];
            wu[k][0] = pack2(w.x, w.y);
            wu[k][1] = pack2(w.z, w.w);
        }
        #pragma unroll
        for (int r = 0; r < 10; ++r) {
            float4 xv = *reinterpret_cast<const float4*>(xrow + r * 16 + 4 * dc);
            ull p0 = splat2(xv.x), p1 = splat2(xv.y);
            ull p2 = splat2(xv.z), p3 = splat2(xv.w);
            if (dc == 0) {                        // bias as addend, no init movs
                FMA2_INIT(acc[r][0], p0, wu[0][0], b0);
                FMA2_INIT(acc[r][1], p0, wu[0][1], b1);
            } else {
                FMA2(acc[r][0], p0, wu[0][0]);
                FMA2(acc[r][1], p0, wu[0][1]);
            }
            FMA2(acc[r][0], p1, wu[1][0]);  FMA2(acc[r][1], p1, wu[1][1]);
            FMA2(acc[r][0], p2, wu[2][0]);  FMA2(acc[r][1], p2, wu[2][1]);
            FMA2(acc[r][0], p3, wu[3][0]);  FMA2(acc[r][1], p3, wu[3][1]);
        }
    }
}

__global__ __launch_bounds__(TPB, 5)
void can_kernel(const float* __restrict__ user,
                const float* __restrict__ item,
                float* __restrict__ out,
                int B)
{
    __shared__ __align__(16) float xs[SPB * X_STRIDE];   // 26.2 KB
    __shared__ __align__(16) float ws[SPB * W_STRIDE];   // 17.9 KB
    __shared__ __align__(8)  ull  mbar;

    const int tid   = threadIdx.x;
    const int sbase = blockIdx.x * SPB;
    const int nsamp = min(SPB, B - sbase);

    unsigned mbar_a = (unsigned)__cvta_generic_to_shared(&mbar);

    // ---- stage x and W via bulk-async DMA ----
    if (tid == 0) {
        asm volatile("mbarrier.init.shared.b64 [%0], 1;" :: "r"(mbar_a) : "memory");
        unsigned bytes = (unsigned)nsamp * (CAN_N * CAN_D + W_FLOATS) * 4u;
        asm volatile("mbarrier.arrive.expect_tx.shared.b64 _, [%0], %1;"
                     :: "r"(mbar_a), "r"(bytes) : "memory");
    }
    __syncthreads();

    if (tid < nsamp * 5) {            // x: 5 blocks of 640B per sample
        int s = tid / 5, rb = tid - s * 5;
        unsigned dst = (unsigned)__cvta_generic_to_shared(
            xs + s * X_STRIDE + rb * XBLK);
        const float* src = user + (size_t)(sbase + s) * (CAN_N * CAN_D) + rb * 160;
        asm volatile(
            "cp.async.bulk.shared::cluster.global.mbarrier::complete_tx::bytes "
            "[%0], [%1], %2, [%3];"
            :: "r"(dst), "l"(src), "r"(640u), "r"(mbar_a) : "memory");
    } else if (tid >= 64 && tid < 64 + nsamp) {   // W: 2176B per sample
        int s = tid - 64;
        unsigned dst = (unsigned)__cvta_generic_to_shared(ws + s * W_STRIDE);
        const float* src = item + (size_t)(sbase + s) * W_FLOATS;
        asm volatile(
            "cp.async.bulk.shared::cluster.global.mbarrier::complete_tx::bytes "
            "[%0], [%1], %2, [%3];"
            :: "r"(dst), "l"(src), "r"(2176u), "r"(mbar_a) : "memory");
    }

    // ---- wait for DMA completion (acquire) ----
    {
        asm volatile(
            "{\n\t"
            ".reg .pred P1;\n\t"
            "WAIT_LOOP_%=:\n\t"
            "mbarrier.try_wait.parity.acquire.cta.shared::cta.b64 P1, [%0], 0, 0x989680;\n\t"
            "@P1 bra.uni WAIT_DONE_%=;\n\t"
            "bra.uni WAIT_LOOP_%=;\n\t"
            "WAIT_DONE_%=:\n\t"
            "}"
            :: "r"(mbar_a) : "memory");
    }

    const int sl = tid / 20;        // local sample
    const int ls = tid - sl * 20;
    const int rg = ls >> 2;         // row group: rows rg*10 .. rg*10+9
    const int ch = ls & 3;          // column quarter: cols ch*4 .. ch*4+3

    if (sl < nsamp) {
        const float4* __restrict__ wl =
            reinterpret_cast<const float4*>(ws + sl * W_STRIDE);
        float* __restrict__ xrow = xs + sl * X_STRIDE + rg * XBLK;
        ull acc[10][2];

        // ---- layer 0: accumulate, relu, write own quarter back in place ----
        can_core(wl, xrow, ch, acc);
        __syncwarp();               // quad finishes reading before overwrite
        #pragma unroll
        for (int r = 0; r < 10; ++r) {
            float f0, f1, f2, f3;
            unpack2(acc[r][0], f0, f1);
            unpack2(acc[r][1], f2, f3);
            *reinterpret_cast<float4*>(xrow + r * 16 + ch * 4) =
                make_float4(fmaxf(f0, 0.f), fmaxf(f1, 0.f),
                            fmaxf(f2, 0.f), fmaxf(f3, 0.f));
        }
        __syncwarp();               // quad writes visible before layer-1 reads

        // ---- layer 1: accumulate, relu, write result back to smem ----
        can_core(wl + 68, xrow, ch, acc);   // layer-1 params at +272 floats
        __syncwarp();               // quad finishes layer-1 reads before overwrite
        #pragma unroll
        for (int r = 0; r < 10; ++r) {
            float f0, f1, f2, f3;
            unpack2(acc[r][0], f0, f1);
            unpack2(acc[r][1], f2, f3);
            *reinterpret_cast<float4*>(xrow + r * 16 + ch * 4) =
                make_float4(fmaxf(f0, 0.f), fmaxf(f1, 0.f),
                            fmaxf(f2, 0.f), fmaxf(f3, 0.f));
        }
    }
    __syncthreads();

    // ---- bulk-store results: 5 x 640B per sample, smem -> global ----
    if (tid < nsamp * 5) {
        asm volatile("fence.proxy.async.shared::cta;" ::: "memory");
        int s = tid / 5, rb = tid - s * 5;
        unsigned src = (unsigned)__cvta_generic_to_shared(
            xs + s * X_STRIDE + rb * XBLK);
        float* dst = out + (size_t)(sbase + s) * (CAN_N * CAN_D) + rb * 160;
        asm volatile(
            "cp.async.bulk.global.shared::cta.bulk_group [%0], [%1], %2;"
            :: "l"(dst), "r"(src), "r"(640u) : "memory");
        asm volatile("cp.async.bulk.commit_group;" ::: "memory");
        asm volatile("cp.async.bulk.wait_group 0;" ::: "memory");
    }
}

extern "C" void kernel_launch(void* const* d_in, const int* in_sizes, int n_in,
                              void* d_out, int out_size)
{
    const float* user = (const float*)d_in[0];
    const float* item = (const float*)d_in[1];
    float* out = (float*)d_out;

    const int B = in_sizes[0] / (CAN_N * CAN_D);   // 16384
    const int grid = (B + SPB - 1) / SPB;

    can_kernel<<<grid, TPB>>>(user, item, out, B);
}

// round 11
// speedup vs baseline: 1.0504x; 1.0504x over previous
#include <cuda_runtime.h>
#include <cstddef>

// CAN: per-sample 2-layer MLP, B=16384, N=50, D=16, fp32.
// x = relu(x @ W0 + b0); x = relu(x @ W1 + b1)
//
// R10: scalar-FFMA rewrite of R8. Quad lane owns 10 rows x 4 cols
// (20 lanes/sample); cp.async staging into padded smem; W window 16 regs;
// bias folded into d=0 FFMA; layer-0 in-place (quad-private, __syncwarp);
// layer-1 stores straight from accumulators. No f32x2 pack/splat/unpack.

#define CAN_D 16
#define CAN_N 50
#define SPB 8                 // samples per block
#define TPB 160               // 8 samples * 20 lanes
#define XBLK 164              // floats per 10-row block (160 data + 4 pad)
#define X_STRIDE 820          // 5 blocks * 164 floats per sample
#define W_FLOATS 544
#define W_STRIDE 560          // mod 32 banks = 16 -> straddle-conflict-free

__device__ __forceinline__ void cp_async16(unsigned dst, const void* src) {
    asm volatile("cp.async.cg.shared.global [%0], [%1], 16;"
                 :: "r"(dst), "l"(src));
}

// One layer for lane's 10 rows x 4 cols, all scalar FFMA.
// wl: float4 view of layer params (W row d quarter ch at idx 4d+ch,
// bias quarter at 64+ch). xrow: lane's 10 rows in smem, stride 16 floats.
__device__ __forceinline__ void can_core(const float4* __restrict__ wl,
                                         const float* __restrict__ xrow,
                                         int ch, float acc[10][4])
{
    const float4 bv = wl[64 + ch];

    // ---- chunk 0 (d = 0..3), d=0 folds the bias in as FFMA addend ----
    {
        float4 w0 = wl[0 * 4 + ch];
        float4 w1 = wl[1 * 4 + ch];
        float4 w2 = wl[2 * 4 + ch];
        float4 w3 = wl[3 * 4 + ch];
        #pragma unroll
        for (int r = 0; r < 10; ++r) {
            float4 xv = *reinterpret_cast<const float4*>(xrow + r * 16);
            acc[r][0] = fmaf(xv.x, w0.x, bv.x);
            acc[r][1] = fmaf(xv.x, w0.y, bv.y);
            acc[r][2] = fmaf(xv.x, w0.z, bv.z);
            acc[r][3] = fmaf(xv.x, w0.w, bv.w);
            acc[r][0] = fmaf(xv.y, w1.x, acc[r][0]);
            acc[r][1] = fmaf(xv.y, w1.y, acc[r][1]);
            acc[r][2] = fmaf(xv.y, w1.z, acc[r][2]);
            acc[r][3] = fmaf(xv.y, w1.w, acc[r][3]);
            acc[r][0] = fmaf(xv.z, w2.x, acc[r][0]);
            acc[r][1] = fmaf(xv.z, w2.y, acc[r][1]);
            acc[r][2] = fmaf(xv.z, w2.z, acc[r][2]);
            acc[r][3] = fmaf(xv.z, w2.w, acc[r][3]);
            acc[r][0] = fmaf(xv.w, w3.x, acc[r][0]);
            acc[r][1] = fmaf(xv.w, w3.y, acc[r][1]);
            acc[r][2] = fmaf(xv.w, w3.z, acc[r][2]);
            acc[r][3] = fmaf(xv.w, w3.w, acc[r][3]);
        }
    }
    // ---- chunks 1..3 (d = 4..15) ----
    #pragma unroll
    for (int dc = 1; dc < 4; ++dc) {
        float4 w0 = wl[(4 * dc + 0) * 4 + ch];
        float4 w1 = wl[(4 * dc + 1) * 4 + ch];
        float4 w2 = wl[(4 * dc + 2) * 4 + ch];
        float4 w3 = wl[(4 * dc + 3) * 4 + ch];
        #pragma unroll
        for (int r = 0; r < 10; ++r) {
            float4 xv = *reinterpret_cast<const float4*>(xrow + r * 16 + 4 * dc);
            acc[r][0] = fmaf(xv.x, w0.x, acc[r][0]);
            acc[r][1] = fmaf(xv.x, w0.y, acc[r][1]);
            acc[r][2] = fmaf(xv.x, w0.z, acc[r][2]);
            acc[r][3] = fmaf(xv.x, w0.w, acc[r][3]);
            acc[r][0] = fmaf(xv.y, w1.x, acc[r][0]);
            acc[r][1] = fmaf(xv.y, w1.y, acc[r][1]);
            acc[r][2] = fmaf(xv.y, w1.z, acc[r][2]);
            acc[r][3] = fmaf(xv.y, w1.w, acc[r][3]);
            acc[r][0] = fmaf(xv.z, w2.x, acc[r][0]);
            acc[r][1] = fmaf(xv.z, w2.y, acc[r][1]);
            acc[r][2] = fmaf(xv.z, w2.z, acc[r][2]);
            acc[r][3] = fmaf(xv.z, w2.w, acc[r][3]);
            acc[r][0] = fmaf(xv.w, w3.x, acc[r][0]);
            acc[r][1] = fmaf(xv.w, w3.y, acc[r][1]);
            acc[r][2] = fmaf(xv.w, w3.z, acc[r][2]);
            acc[r][3] = fmaf(xv.w, w3.w, acc[r][3]);
        }
    }
}

__global__ __launch_bounds__(TPB, 5)
void can_kernel(const float* __restrict__ user,
                const float* __restrict__ item,
                float* __restrict__ out,
                int B)
{
    __shared__ __align__(16) float xs[SPB * X_STRIDE];   // 26.2 KB
    __shared__ __align__(16) float ws[SPB * W_STRIDE];   // 17.9 KB

    const int tid   = threadIdx.x;
    const int sbase = blockIdx.x * SPB;
    const int nsamp = min(SPB, B - sbase);
    const int nf4   = nsamp * 200;                        // <= 1600
    const int nw4   = nsamp * 136;                        // <= 1088

    // ---- stage x and W via cp.async (no register round-trip) ----
    {
        const float4* __restrict__ gx =
            reinterpret_cast<const float4*>(user + (size_t)sbase * (CAN_N * CAN_D));
        #pragma unroll
        for (int k = 0; k < 10; ++k) {
            int i = tid + k * TPB;
            if (i < nf4) {
                int s = i / 200, f = i - s * 200;
                int row = f >> 2, q = f & 3;
                int rb = row / 10, rr = row - rb * 10;
                unsigned dst = (unsigned)__cvta_generic_to_shared(
                    xs + s * X_STRIDE + rb * XBLK + rr * 16 + q * 4);
                cp_async16(dst, gx + i);
            }
        }
        const float4* __restrict__ gw =
            reinterpret_cast<const float4*>(item + (size_t)sbase * W_FLOATS);
        #pragma unroll
        for (int k = 0; k < 7; ++k) {
            int i = tid + k * TPB;
            if (i < nw4) {
                int s = i / 136, f = i - s * 136;
                unsigned dst = (unsigned)__cvta_generic_to_shared(
                    ws + s * W_STRIDE + f * 4);
                cp_async16(dst, gw + i);
            }
        }
        asm volatile("cp.async.commit_group;" ::: "memory");
        asm volatile("cp.async.wait_group 0;"  ::: "memory");
    }
    __syncthreads();

    const int sl = tid / 20;        // local sample
    const int ls = tid - sl * 20;
    const int rg = ls >> 2;         // row group: rows rg*10 .. rg*10+9
    const int ch = ls & 3;          // column quarter: cols ch*4 .. ch*4+3

    if (sl < nsamp) {
        const float4* __restrict__ wl =
            reinterpret_cast<const float4*>(ws + sl * W_STRIDE);
        float* __restrict__ xrow = xs + sl * X_STRIDE + rg * XBLK;
        float acc[10][4];

        // ---- layer 0: accumulate, relu, write own quarter back in place ----
        can_core(wl, xrow, ch, acc);
        __syncwarp();               // quad finishes reading before overwrite
        #pragma unroll
        for (int r = 0; r < 10; ++r) {
            *reinterpret_cast<float4*>(xrow + r * 16 + ch * 4) =
                make_float4(fmaxf(acc[r][0], 0.f), fmaxf(acc[r][1], 0.f),
                            fmaxf(acc[r][2], 0.f), fmaxf(acc[r][3], 0.f));
        }
        __syncwarp();               // quad writes visible before layer-1 reads

        // ---- layer 1: accumulate, relu, store straight to global ----
        can_core(wl + 68, xrow, ch, acc);   // layer-1 params at +272 floats
        float* __restrict__ gout = out + (size_t)(sbase + sl) * (CAN_N * CAN_D)
                                 + (rg * 10) * CAN_D + ch * 4;
        #pragma unroll
        for (int r = 0; r < 10; ++r) {
            *reinterpret_cast<float4*>(gout + r * CAN_D) =
                make_float4(fmaxf(acc[r][0], 0.f), fmaxf(acc[r][1], 0.f),
                            fmaxf(acc[r][2], 0.f), fmaxf(acc[r][3], 0.f));
        }
    }
}

extern "C" void kernel_launch(void* const* d_in, const int* in_sizes, int n_in,
                              void* d_out, int out_size)
{
    const float* user = (const float*)d_in[0];
    const float* item = (const float*)d_in[1];
    float* out = (float*)d_out;

    const int B = in_sizes[0] / (CAN_N * CAN_D);   // 16384
    const int grid = (B + SPB - 1) / SPB;

    can_kernel<<<grid, TPB>>>(user, item, out, B);
}